// round 11
// baseline (speedup 1.0000x reference)
#include <cuda_runtime.h>
#include <cuda_bf16.h>
#include <mma.h>
#include <math.h>
#include <stdint.h>

using namespace nvcuda;

#define N_TOK 2048
#define DMODEL 512
#define NH 8
#define DH 64
#define FF 2
#define HH 32
#define WW 32

// ---------------------------------------------------------------------------
// Device scratch (no allocations allowed). Referenced ONLY in device code.
// ---------------------------------------------------------------------------
__device__ __align__(128) float g_qkv[N_TOK * 3 * DMODEL];
__device__ __align__(128) __nv_bfloat16 g_xhi[N_TOK * DMODEL];
__device__ __align__(128) __nv_bfloat16 g_xlo[N_TOK * DMODEL];
__device__ __align__(128) __nv_bfloat16 g_wq_hi[DMODEL * 3 * DMODEL];  // [512][1536]
__device__ __align__(128) __nv_bfloat16 g_wq_lo[DMODEL * 3 * DMODEL];
__device__ __align__(128) __nv_bfloat16 g_wo_hi[DMODEL * DMODEL];      // [512][512]
__device__ __align__(128) __nv_bfloat16 g_wo_lo[DMODEL * DMODEL];
__device__ __align__(128) __nv_bfloat16 g_ah_hi[N_TOK * DMODEL];
__device__ __align__(128) __nv_bfloat16 g_ah_lo[N_TOK * DMODEL];

__device__ __forceinline__ void split2(float v, __nv_bfloat16& h, __nv_bfloat16& l) {
    h = __float2bfloat16(v);
    l = __float2bfloat16(v - __bfloat162float(h));
}

// ---------------------------------------------------------------------------
// Prep: elementwise hi/lo split. Destination resolved in device code.
// ---------------------------------------------------------------------------
__device__ __forceinline__ void split_body(const float* __restrict__ src,
                                           __nv_bfloat16* dhi, __nv_bfloat16* dlo) {
    int i = blockIdx.x * blockDim.x + threadIdx.x;
    float4 v = ((const float4*)src)[i];
    __nv_bfloat16 h0, l0, h1, l1, h2, l2, h3, l3;
    split2(v.x, h0, l0); split2(v.y, h1, l1);
    split2(v.z, h2, l2); split2(v.w, h3, l3);
    __nv_bfloat162* hi = (__nv_bfloat162*)dhi;
    __nv_bfloat162* lo = (__nv_bfloat162*)dlo;
    hi[2 * i + 0] = __nv_bfloat162(h0, h1);
    hi[2 * i + 1] = __nv_bfloat162(h2, h3);
    lo[2 * i + 0] = __nv_bfloat162(l0, l1);
    lo[2 * i + 1] = __nv_bfloat162(l2, l3);
}

__global__ void split_x_kernel(const float* __restrict__ src)  { split_body(src, g_xhi, g_xlo); }
__global__ void split_wq_kernel(const float* __restrict__ src) { split_body(src, g_wq_hi, g_wq_lo); }
__global__ void split_wo_kernel(const float* __restrict__ src) { split_body(src, g_wo_hi, g_wo_lo); }

// ---------------------------------------------------------------------------
// WMMA GEMM body: C[M,Ncols] = A[M,512](hi+lo) @ W[512,Ncols](hi+lo)
// CTA 128x128, 8 warps (4m x 2n), warp 32x64, k-chunk 16, static smem (~21KB).
// All global-scratch pointers are formed in device code by the callers.
// ---------------------------------------------------------------------------
#define ARS 24    // A smem row stride (halves): 48B rows
#define BRS 136   // B smem row stride (halves): 272B rows

__device__ __forceinline__ void wmma_gemm_body(
    const __nv_bfloat16* Ahi, const __nv_bfloat16* Alo,
    const __nv_bfloat16* Whi, const __nv_bfloat16* Wlo,
    float* C, int Ncols) {
    __shared__ __align__(16) __nv_bfloat16 sAh[128 * ARS];
    __shared__ __align__(16) __nv_bfloat16 sAl[128 * ARS];
    __shared__ __align__(16) __nv_bfloat16 sBh[16 * BRS];
    __shared__ __align__(16) __nv_bfloat16 sBl[16 * BRS];

    const int tid = threadIdx.x;
    const int w = tid >> 5;
    const int warpm = w & 3, warpn = w >> 2;
    const int row0 = blockIdx.y * 128, col0 = blockIdx.x * 128;

    wmma::fragment<wmma::accumulator, 16, 16, 16, float> acc[2][4];
#pragma unroll
    for (int mt = 0; mt < 2; mt++)
#pragma unroll
        for (int nt = 0; nt < 4; nt++)
            wmma::fill_fragment(acc[mt][nt], 0.0f);

    const int ar = tid >> 1, aco = (tid & 1) * 8;      // A: 128 rows x 2 chunks
    const int br = tid >> 4, bco = (tid & 15) * 8;     // B: 16 rows x 16 chunks

    for (int kc = 0; kc < 32; kc++) {
        const int k0 = kc * 16;
        *(uint4*)&sAh[ar * ARS + aco] =
            *(const uint4*)&Ahi[(size_t)(row0 + ar) * 512 + k0 + aco];
        *(uint4*)&sAl[ar * ARS + aco] =
            *(const uint4*)&Alo[(size_t)(row0 + ar) * 512 + k0 + aco];
        *(uint4*)&sBh[br * BRS + bco] =
            *(const uint4*)&Whi[(size_t)(k0 + br) * Ncols + col0 + bco];
        *(uint4*)&sBl[br * BRS + bco] =
            *(const uint4*)&Wlo[(size_t)(k0 + br) * Ncols + col0 + bco];
        __syncthreads();

        wmma::fragment<wmma::matrix_a, 16, 16, 16, __nv_bfloat16, wmma::row_major>
            fah[2], fal[2];
#pragma unroll
        for (int mt = 0; mt < 2; mt++) {
            wmma::load_matrix_sync(fah[mt], &sAh[(warpm * 32 + mt * 16) * ARS], ARS);
            wmma::load_matrix_sync(fal[mt], &sAl[(warpm * 32 + mt * 16) * ARS], ARS);
        }
#pragma unroll
        for (int nt = 0; nt < 4; nt++) {
            wmma::fragment<wmma::matrix_b, 16, 16, 16, __nv_bfloat16, wmma::row_major>
                fbh, fbl;
            wmma::load_matrix_sync(fbh, &sBh[warpn * 64 + nt * 16], BRS);
            wmma::load_matrix_sync(fbl, &sBl[warpn * 64 + nt * 16], BRS);
#pragma unroll
            for (int mt = 0; mt < 2; mt++) {
                wmma::mma_sync(acc[mt][nt], fah[mt], fbh, acc[mt][nt]);
                wmma::mma_sync(acc[mt][nt], fah[mt], fbl, acc[mt][nt]);
                wmma::mma_sync(acc[mt][nt], fal[mt], fbh, acc[mt][nt]);
            }
        }
        __syncthreads();
    }

#pragma unroll
    for (int mt = 0; mt < 2; mt++)
#pragma unroll
        for (int nt = 0; nt < 4; nt++)
            wmma::store_matrix_sync(
                &C[(size_t)(row0 + warpm * 32 + mt * 16) * Ncols +
                   col0 + warpn * 64 + nt * 16],
                acc[mt][nt], Ncols, wmma::mem_row_major);
}

__global__ __launch_bounds__(256) void qkv_wmma_kernel() {
    wmma_gemm_body(g_xhi, g_xlo, g_wq_hi, g_wq_lo, g_qkv, 3 * DMODEL);
}
__global__ __launch_bounds__(256) void out_wmma_kernel(float* __restrict__ C) {
    wmma_gemm_body(g_ah_hi, g_ah_lo, g_wo_hi, g_wo_lo, C, DMODEL);
}

// Bias add (in place on out): one float4 per thread. Both args harness pointers.
__global__ void bias_add_kernel(float* __restrict__ C, const float* __restrict__ bias) {
    int i = blockIdx.x * blockDim.x + threadIdx.x;     // over N_TOK*DMODEL/4
    int c4 = (i & (DMODEL / 4 - 1)) * 4;
    float4 v = ((float4*)C)[i];
    v.x += bias[c4 + 0]; v.y += bias[c4 + 1];
    v.z += bias[c4 + 2]; v.w += bias[c4 + 3];
    ((float4*)C)[i] = v;
}

// ---------------------------------------------------------------------------
// Attention (proven structure; emits bf16 hi/lo for the out GEMM)
// ---------------------------------------------------------------------------
__global__ void attn_kernel() {
    const float* __restrict__ qkv = g_qkv;
    int r = blockIdx.x;            // 0..63 : (f*32 + h)
    int h = blockIdx.y;            // head
    int f = r >> 5;
    int hp = r & 31;
    int i0 = r * 32;
    int tid = threadIdx.x;
    int ql = tid >> 3;             // query (w coordinate)
    int g  = tid & 7;              // dim group
    int hoff = h * DH;

    __shared__ float Ks[64][33];
    __shared__ float Vs[64][33];

    int iq = i0 + ql;
    int t  = iq + 1;
    const float scale = 0.125f;

    float q[8];
    if (t < N_TOK) {
#pragma unroll
        for (int d = 0; d < 8; d++)
            q[d] = qkv[(size_t)t * 1536 + hoff + g * 8 + d] * scale;
    } else {
#pragma unroll
        for (int d = 0; d < 8; d++) q[d] = 0.f;
    }

    float m, l, acc[8];
    {
        float s = 0.f;
#pragma unroll
        for (int d = 0; d < 8; d++)
            s += q[d] * qkv[512 + hoff + g * 8 + d];
        s += __shfl_xor_sync(0xffffffffu, s, 1);
        s += __shfl_xor_sync(0xffffffffu, s, 2);
        s += __shfl_xor_sync(0xffffffffu, s, 4);
        m = s; l = 1.f;
#pragma unroll
        for (int d = 0; d < 8; d++)
            acc[d] = qkv[1024 + hoff + g * 8 + d];
    }

    for (int df = -2; df <= 2; df++) {
        int nf = f + df;
        if (nf < 0 || nf >= FF) continue;
        for (int dh = -2; dh <= 2; dh++) {
            int nh = hp + dh;
            if (nh < 0 || nh >= HH) continue;
            int j0 = (nf * HH + nh) * WW;

            __syncthreads();
#pragma unroll
            for (int i = 0; i < 2; i++) {
                int id4 = tid + i * 256;
                int c  = id4 >> 4;
                int dv = (id4 & 15) << 2;
                int tok = j0 + 1 + c;
                float4 kk, vv;
                if (tok < N_TOK) {
                    kk = *(const float4*)&qkv[(size_t)tok * 1536 + 512 + hoff + dv];
                    vv = *(const float4*)&qkv[(size_t)tok * 1536 + 1024 + hoff + dv];
                } else {
                    kk = make_float4(0.f, 0.f, 0.f, 0.f);
                    vv = kk;
                }
                Ks[dv + 0][c] = kk.x; Ks[dv + 1][c] = kk.y;
                Ks[dv + 2][c] = kk.z; Ks[dv + 3][c] = kk.w;
                Vs[dv + 0][c] = vv.x; Vs[dv + 1][c] = vv.y;
                Vs[dv + 2][c] = vv.z; Vs[dv + 3][c] = vv.w;
            }
            __syncthreads();

#pragma unroll
            for (int dw = -2; dw <= 2; dw++) {
                int c = ql + dw;
                int j = j0 + c;
                bool valid = ((unsigned)c < 32u) && (j <= iq);
                int cc = min(max(c, 0), 31);
                float s = 0.f;
#pragma unroll
                for (int d = 0; d < 8; d++)
                    s += q[d] * Ks[g * 8 + d][cc];
                s += __shfl_xor_sync(0xffffffffu, s, 1);
                s += __shfl_xor_sync(0xffffffffu, s, 2);
                s += __shfl_xor_sync(0xffffffffu, s, 4);
                if (valid) {
                    float mn = fmaxf(m, s);
                    float corr = __expf(m - mn);
                    float p = __expf(s - mn);
                    l = l * corr + p;
#pragma unroll
                    for (int d = 0; d < 8; d++)
                        acc[d] = acc[d] * corr + p * Vs[g * 8 + d][cc];
                    m = mn;
                }
            }
        }
    }

    if (t < N_TOK) {
        float inv = 1.f / l;
#pragma unroll
        for (int d = 0; d < 8; d++) {
            float v = acc[d] * inv;
            __nv_bfloat16 h16, l16;
            split2(v, h16, l16);
            size_t idx = (size_t)t * DMODEL + hoff + g * 8 + d;
            g_ah_hi[idx] = h16;
            g_ah_lo[idx] = l16;
        }
    }
}

// Output row 0 = V of token 0 (BOS passthrough)
__global__ void bos_kernel() {
    int d = threadIdx.x;           // 512 threads
    float v = g_qkv[1024 + d];
    __nv_bfloat16 h16, l16;
    split2(v, h16, l16);
    g_ah_hi[d] = h16;
    g_ah_lo[d] = l16;
}

// ---------------------------------------------------------------------------
extern "C" void kernel_launch(void* const* d_in, const int* in_sizes, int n_in,
                              void* d_out, int out_size) {
    const float* x     = (const float*)d_in[0];   // [1,2048,512]
    const float* w_qkv = (const float*)d_in[1];   // [512,1536]
    const float* w_out = (const float*)d_in[2];   // [512,512]
    const float* b_out = (const float*)d_in[3];   // [512]
    float* out = (float*)d_out;                   // [1,2048,512]

    // Prep: hi/lo splits (destinations are device globals, bound in device code)
    split_x_kernel<<<N_TOK * DMODEL / 4 / 512, 512>>>(x);
    split_wq_kernel<<<DMODEL * 3 * DMODEL / 4 / 512, 512>>>(w_qkv);
    split_wo_kernel<<<DMODEL * DMODEL / 4 / 512, 512>>>(w_out);

    // QKV GEMM: [2048,512] @ [512,1536]
    qkv_wmma_kernel<<<dim3(1536 / 128, N_TOK / 128), 256>>>();

    attn_kernel<<<dim3(64, NH), 256>>>();
    bos_kernel<<<1, 512>>>();

    // Out GEMM: [2048,512] @ [512,512], then bias
    out_wmma_kernel<<<dim3(DMODEL / 128, N_TOK / 128), 256>>>(out);
    bias_add_kernel<<<N_TOK * DMODEL / 4 / 512, 512>>>(out, b_out);
}

// round 13
// speedup vs baseline: 1.4652x; 1.4652x over previous
#include <cuda_runtime.h>
#include <cuda_bf16.h>
#include <mma.h>
#include <math.h>
#include <stdint.h>

using namespace nvcuda;

#define N_TOK 2048
#define DMODEL 512
#define NH 8
#define DH 64
#define FF 2
#define HH 32
#define WW 32

// ---------------------------------------------------------------------------
// Device scratch (no allocations allowed). Referenced ONLY in device code.
// ---------------------------------------------------------------------------
__device__ __align__(128) float g_qkv[N_TOK * 3 * DMODEL];
__device__ __align__(128) __nv_bfloat16 g_xhi[N_TOK * DMODEL];
__device__ __align__(128) __nv_bfloat16 g_xlo[N_TOK * DMODEL];
__device__ __align__(128) __nv_bfloat16 g_wq_hi[DMODEL * 3 * DMODEL];  // [512][1536]
__device__ __align__(128) __nv_bfloat16 g_wq_lo[DMODEL * 3 * DMODEL];
__device__ __align__(128) __nv_bfloat16 g_wo_hi[DMODEL * DMODEL];      // [512][512]
__device__ __align__(128) __nv_bfloat16 g_wo_lo[DMODEL * DMODEL];
__device__ __align__(128) __nv_bfloat16 g_ah_hi[N_TOK * DMODEL];
__device__ __align__(128) __nv_bfloat16 g_ah_lo[N_TOK * DMODEL];

__device__ __forceinline__ void split2(float v, __nv_bfloat16& h, __nv_bfloat16& l) {
    h = __float2bfloat16(v);
    l = __float2bfloat16(v - __bfloat162float(h));
}

#define CP_ASYNC16(dst, src) \
    asm volatile("cp.async.cg.shared.global [%0], [%1], 16;" \
                 :: "r"(dst), "l"(src) : "memory")
#define CP_COMMIT() asm volatile("cp.async.commit_group;" ::: "memory")
#define CP_WAIT0()  asm volatile("cp.async.wait_group 0;" ::: "memory")

__device__ __forceinline__ uint32_t smem_u32(const void* p) {
    uint32_t a;
    asm("{ .reg .u64 t; cvta.to.shared.u64 t, %1; cvt.u32.u64 %0, t; }"
        : "=r"(a) : "l"(p));
    return a;
}

// ---------------------------------------------------------------------------
// Prep: elementwise hi/lo split. Destination resolved in device code.
// ---------------------------------------------------------------------------
__device__ __forceinline__ void split_body(const float* __restrict__ src,
                                           __nv_bfloat16* dhi, __nv_bfloat16* dlo) {
    int i = blockIdx.x * blockDim.x + threadIdx.x;
    float4 v = ((const float4*)src)[i];
    __nv_bfloat16 h0, l0, h1, l1, h2, l2, h3, l3;
    split2(v.x, h0, l0); split2(v.y, h1, l1);
    split2(v.z, h2, l2); split2(v.w, h3, l3);
    __nv_bfloat162* hi = (__nv_bfloat162*)dhi;
    __nv_bfloat162* lo = (__nv_bfloat162*)dlo;
    hi[2 * i + 0] = __nv_bfloat162(h0, h1);
    hi[2 * i + 1] = __nv_bfloat162(h2, h3);
    lo[2 * i + 0] = __nv_bfloat162(l0, l1);
    lo[2 * i + 1] = __nv_bfloat162(l2, l3);
}

__global__ void split_x_kernel(const float* __restrict__ src)  { split_body(src, g_xhi, g_xlo); }
__global__ void split_wq_kernel(const float* __restrict__ src) { split_body(src, g_wq_hi, g_wq_lo); }
__global__ void split_wo_kernel(const float* __restrict__ src) { split_body(src, g_wo_hi, g_wo_lo); }

// ---------------------------------------------------------------------------
// Pipelined WMMA GEMM: C[M,Ncols] = A[M,512](hi+lo) @ W[512,Ncols](hi+lo)
// CTA 128x128, 8 warps (4m x 2n), warp 32x64, k-chunk 16.
// 2-stage cp.async double buffer, one __syncthreads per iteration.
// ---------------------------------------------------------------------------
#define ARS 24    // A smem row stride (halves): 48B rows, conflict-free
#define BRS 136   // B smem row stride (halves): 272B rows, conflict-free

__device__ __forceinline__ void wmma_gemm_body(
    const __nv_bfloat16* Ahi, const __nv_bfloat16* Alo,
    const __nv_bfloat16* Whi, const __nv_bfloat16* Wlo,
    float* C, int Ncols) {
    __shared__ __align__(16) __nv_bfloat16 sAh[2][128 * ARS];
    __shared__ __align__(16) __nv_bfloat16 sAl[2][128 * ARS];
    __shared__ __align__(16) __nv_bfloat16 sBh[2][16 * BRS];
    __shared__ __align__(16) __nv_bfloat16 sBl[2][16 * BRS];

    const int tid = threadIdx.x;
    const int w = tid >> 5;
    const int warpm = w & 3, warpn = w >> 2;
    const int row0 = blockIdx.y * 128, col0 = blockIdx.x * 128;

    wmma::fragment<wmma::accumulator, 16, 16, 16, float> acc[2][4];
#pragma unroll
    for (int mt = 0; mt < 2; mt++)
#pragma unroll
        for (int nt = 0; nt < 4; nt++)
            wmma::fill_fragment(acc[mt][nt], 0.0f);

    const int ar = tid >> 1, aco = (tid & 1) * 8;      // A: 128 rows x 2 chunks
    const int br = tid >> 4, bco = (tid & 15) * 8;     // B: 16 rows x 16 chunks

    const uint32_t dAh = smem_u32(&sAh[0][0]) + (uint32_t)(ar * ARS + aco) * 2;
    const uint32_t dAl = smem_u32(&sAl[0][0]) + (uint32_t)(ar * ARS + aco) * 2;
    const uint32_t dBh = smem_u32(&sBh[0][0]) + (uint32_t)(br * BRS + bco) * 2;
    const uint32_t dBl = smem_u32(&sBl[0][0]) + (uint32_t)(br * BRS + bco) * 2;
    const uint32_t aStageB = (uint32_t)(128 * ARS * 2);
    const uint32_t bStageB = (uint32_t)(16 * BRS * 2);

    const __nv_bfloat16* gAh = Ahi + (size_t)(row0 + ar) * 512 + aco;
    const __nv_bfloat16* gAl = Alo + (size_t)(row0 + ar) * 512 + aco;
    const __nv_bfloat16* gBh = Whi + (size_t)br * Ncols + col0 + bco;
    const __nv_bfloat16* gBl = Wlo + (size_t)br * Ncols + col0 + bco;
    const size_t bStep = (size_t)16 * Ncols;

    auto prefetch = [&](int kc) {
        const int st = kc & 1;
        const int k0 = kc * 16;
        CP_ASYNC16(dAh + st * aStageB, gAh + k0);
        CP_ASYNC16(dAl + st * aStageB, gAl + k0);
        CP_ASYNC16(dBh + st * bStageB, gBh + (size_t)kc * bStep);
        CP_ASYNC16(dBl + st * bStageB, gBl + (size_t)kc * bStep);
        CP_COMMIT();
    };

    prefetch(0);

    for (int kc = 0; kc < 32; kc++) {
        const int st = kc & 1;
        CP_WAIT0();              // stage kc arrived (one group in flight)
        __syncthreads();         // visible to all; stage kc-1 reads retired
        if (kc + 1 < 32) prefetch(kc + 1);   // overlaps with compute below

        wmma::fragment<wmma::matrix_a, 16, 16, 16, __nv_bfloat16, wmma::row_major>
            fah[2], fal[2];
#pragma unroll
        for (int mt = 0; mt < 2; mt++) {
            wmma::load_matrix_sync(fah[mt], &sAh[st][(warpm * 32 + mt * 16) * ARS], ARS);
            wmma::load_matrix_sync(fal[mt], &sAl[st][(warpm * 32 + mt * 16) * ARS], ARS);
        }
#pragma unroll
        for (int nt = 0; nt < 4; nt++) {
            wmma::fragment<wmma::matrix_b, 16, 16, 16, __nv_bfloat16, wmma::row_major>
                fbh, fbl;
            wmma::load_matrix_sync(fbh, &sBh[st][warpn * 64 + nt * 16], BRS);
            wmma::load_matrix_sync(fbl, &sBl[st][warpn * 64 + nt * 16], BRS);
#pragma unroll
            for (int mt = 0; mt < 2; mt++) {
                wmma::mma_sync(acc[mt][nt], fah[mt], fbh, acc[mt][nt]);
                wmma::mma_sync(acc[mt][nt], fah[mt], fbl, acc[mt][nt]);
                wmma::mma_sync(acc[mt][nt], fal[mt], fbh, acc[mt][nt]);
            }
        }
    }

#pragma unroll
    for (int mt = 0; mt < 2; mt++)
#pragma unroll
        for (int nt = 0; nt < 4; nt++)
            wmma::store_matrix_sync(
                &C[(size_t)(row0 + warpm * 32 + mt * 16) * Ncols +
                   col0 + warpn * 64 + nt * 16],
                acc[mt][nt], Ncols, wmma::mem_row_major);
}

__global__ __launch_bounds__(256) void qkv_wmma_kernel() {
    wmma_gemm_body(g_xhi, g_xlo, g_wq_hi, g_wq_lo, g_qkv, 3 * DMODEL);
}
__global__ __launch_bounds__(256) void out_wmma_kernel(float* __restrict__ C) {
    wmma_gemm_body(g_ah_hi, g_ah_lo, g_wo_hi, g_wo_lo, C, DMODEL);
}

// Bias add (in place on out): one float4 per thread.
__global__ void bias_add_kernel(float* __restrict__ C, const float* __restrict__ bias) {
    int i = blockIdx.x * blockDim.x + threadIdx.x;     // over N_TOK*DMODEL/4
    int c4 = (i & (DMODEL / 4 - 1)) * 4;
    float4 v = ((float4*)C)[i];
    v.x += bias[c4 + 0]; v.y += bias[c4 + 1];
    v.z += bias[c4 + 2]; v.w += bias[c4 + 3];
    ((float4*)C)[i] = v;
}

// ---------------------------------------------------------------------------
// Attention (proven structure; emits bf16 hi/lo for the out GEMM)
// ---------------------------------------------------------------------------
__global__ void attn_kernel() {
    const float* __restrict__ qkv = g_qkv;
    int r = blockIdx.x;            // 0..63 : (f*32 + h)
    int h = blockIdx.y;            // head
    int f = r >> 5;
    int hp = r & 31;
    int i0 = r * 32;
    int tid = threadIdx.x;
    int ql = tid >> 3;             // query (w coordinate)
    int g  = tid & 7;              // dim group
    int hoff = h * DH;

    __shared__ float Ks[64][33];
    __shared__ float Vs[64][33];

    int iq = i0 + ql;
    int t  = iq + 1;
    const float scale = 0.125f;

    float q[8];
    if (t < N_TOK) {
#pragma unroll
        for (int d = 0; d < 8; d++)
            q[d] = qkv[(size_t)t * 1536 + hoff + g * 8 + d] * scale;
    } else {
#pragma unroll
        for (int d = 0; d < 8; d++) q[d] = 0.f;
    }

    float m, l, acc[8];
    {
        float s = 0.f;
#pragma unroll
        for (int d = 0; d < 8; d++)
            s += q[d] * qkv[512 + hoff + g * 8 + d];
        s += __shfl_xor_sync(0xffffffffu, s, 1);
        s += __shfl_xor_sync(0xffffffffu, s, 2);
        s += __shfl_xor_sync(0xffffffffu, s, 4);
        m = s; l = 1.f;
#pragma unroll
        for (int d = 0; d < 8; d++)
            acc[d] = qkv[1024 + hoff + g * 8 + d];
    }

    for (int df = -2; df <= 2; df++) {
        int nf = f + df;
        if (nf < 0 || nf >= FF) continue;
        for (int dh = -2; dh <= 2; dh++) {
            int nh = hp + dh;
            if (nh < 0 || nh >= HH) continue;
            int j0 = (nf * HH + nh) * WW;

            __syncthreads();
#pragma unroll
            for (int i = 0; i < 2; i++) {
                int id4 = tid + i * 256;
                int c  = id4 >> 4;
                int dv = (id4 & 15) << 2;
                int tok = j0 + 1 + c;
                float4 kk, vv;
                if (tok < N_TOK) {
                    kk = *(const float4*)&qkv[(size_t)tok * 1536 + 512 + hoff + dv];
                    vv = *(const float4*)&qkv[(size_t)tok * 1536 + 1024 + hoff + dv];
                } else {
                    kk = make_float4(0.f, 0.f, 0.f, 0.f);
                    vv = kk;
                }
                Ks[dv + 0][c] = kk.x; Ks[dv + 1][c] = kk.y;
                Ks[dv + 2][c] = kk.z; Ks[dv + 3][c] = kk.w;
                Vs[dv + 0][c] = vv.x; Vs[dv + 1][c] = vv.y;
                Vs[dv + 2][c] = vv.z; Vs[dv + 3][c] = vv.w;
            }
            __syncthreads();

#pragma unroll
            for (int dw = -2; dw <= 2; dw++) {
                int c = ql + dw;
                int j = j0 + c;
                bool valid = ((unsigned)c < 32u) && (j <= iq);
                int cc = min(max(c, 0), 31);
                float s = 0.f;
#pragma unroll
                for (int d = 0; d < 8; d++)
                    s += q[d] * Ks[g * 8 + d][cc];
                s += __shfl_xor_sync(0xffffffffu, s, 1);
                s += __shfl_xor_sync(0xffffffffu, s, 2);
                s += __shfl_xor_sync(0xffffffffu, s, 4);
                if (valid) {
                    float mn = fmaxf(m, s);
                    float corr = __expf(m - mn);
                    float p = __expf(s - mn);
                    l = l * corr + p;
#pragma unroll
                    for (int d = 0; d < 8; d++)
                        acc[d] = acc[d] * corr + p * Vs[g * 8 + d][cc];
                    m = mn;
                }
            }
        }
    }

    if (t < N_TOK) {
        float inv = 1.f / l;
#pragma unroll
        for (int d = 0; d < 8; d++) {
            float v = acc[d] * inv;
            __nv_bfloat16 h16, l16;
            split2(v, h16, l16);
            size_t idx = (size_t)t * DMODEL + hoff + g * 8 + d;
            g_ah_hi[idx] = h16;
            g_ah_lo[idx] = l16;
        }
    }
}

// Output row 0 = V of token 0 (BOS passthrough)
__global__ void bos_kernel() {
    int d = threadIdx.x;           // 512 threads
    float v = g_qkv[1024 + d];
    __nv_bfloat16 h16, l16;
    split2(v, h16, l16);
    g_ah_hi[d] = h16;
    g_ah_lo[d] = l16;
}

// ---------------------------------------------------------------------------
extern "C" void kernel_launch(void* const* d_in, const int* in_sizes, int n_in,
                              void* d_out, int out_size) {
    const float* x     = (const float*)d_in[0];   // [1,2048,512]
    const float* w_qkv = (const float*)d_in[1];   // [512,1536]
    const float* w_out = (const float*)d_in[2];   // [512,512]
    const float* b_out = (const float*)d_in[3];   // [512]
    float* out = (float*)d_out;                   // [1,2048,512]

    split_x_kernel<<<N_TOK * DMODEL / 4 / 512, 512>>>(x);
    split_wq_kernel<<<DMODEL * 3 * DMODEL / 4 / 512, 512>>>(w_qkv);
    split_wo_kernel<<<DMODEL * DMODEL / 4 / 512, 512>>>(w_out);

    qkv_wmma_kernel<<<dim3(1536 / 128, N_TOK / 128), 256>>>();

    attn_kernel<<<dim3(64, NH), 256>>>();
    bos_kernel<<<1, 512>>>();

    out_wmma_kernel<<<dim3(DMODEL / 128, N_TOK / 128), 256>>>(out);
    bias_add_kernel<<<N_TOK * DMODEL / 4 / 512, 512>>>(out, b_out);
}

// round 14
// speedup vs baseline: 1.7981x; 1.2272x over previous
#include <cuda_runtime.h>
#include <cuda_bf16.h>
#include <mma.h>
#include <math.h>
#include <stdint.h>

using namespace nvcuda;

#define N_TOK 2048
#define DMODEL 512
#define NH 8
#define DH 64
#define FF 2
#define HH 32
#define WW 32

// ---------------------------------------------------------------------------
// Device scratch (no allocations allowed). Referenced ONLY in device code.
// ---------------------------------------------------------------------------
__device__ __align__(128) float g_qkv[N_TOK * 3 * DMODEL];
__device__ __align__(128) __nv_bfloat16 g_xhi[N_TOK * DMODEL];
__device__ __align__(128) __nv_bfloat16 g_xlo[N_TOK * DMODEL];
__device__ __align__(128) __nv_bfloat16 g_wq_hi[DMODEL * 3 * DMODEL];  // [512][1536]
__device__ __align__(128) __nv_bfloat16 g_wq_lo[DMODEL * 3 * DMODEL];
__device__ __align__(128) __nv_bfloat16 g_wo_hi[DMODEL * DMODEL];      // [512][512]
__device__ __align__(128) __nv_bfloat16 g_wo_lo[DMODEL * DMODEL];
__device__ __align__(128) __nv_bfloat16 g_ah_hi[N_TOK * DMODEL];
__device__ __align__(128) __nv_bfloat16 g_ah_lo[N_TOK * DMODEL];

__device__ __forceinline__ void split2(float v, __nv_bfloat16& h, __nv_bfloat16& l) {
    h = __float2bfloat16(v);
    l = __float2bfloat16(v - __bfloat162float(h));
}

#define CP_ASYNC16(dst, src) \
    asm volatile("cp.async.cg.shared.global [%0], [%1], 16;" \
                 :: "r"(dst), "l"(src) : "memory")
#define CP_COMMIT() asm volatile("cp.async.commit_group;" ::: "memory")
#define CP_WAIT1()  asm volatile("cp.async.wait_group 1;" ::: "memory")
#define CP_WAIT0()  asm volatile("cp.async.wait_group 0;" ::: "memory")

__device__ __forceinline__ uint32_t smem_u32(const void* p) {
    uint32_t a;
    asm("{ .reg .u64 t; cvta.to.shared.u64 t, %1; cvt.u32.u64 %0, t; }"
        : "=r"(a) : "l"(p));
    return a;
}

// ---------------------------------------------------------------------------
// Prep: elementwise hi/lo split. Destination resolved in device code.
// ---------------------------------------------------------------------------
__device__ __forceinline__ void split_body(const float* __restrict__ src,
                                           __nv_bfloat16* dhi, __nv_bfloat16* dlo) {
    int i = blockIdx.x * blockDim.x + threadIdx.x;
    float4 v = ((const float4*)src)[i];
    __nv_bfloat16 h0, l0, h1, l1, h2, l2, h3, l3;
    split2(v.x, h0, l0); split2(v.y, h1, l1);
    split2(v.z, h2, l2); split2(v.w, h3, l3);
    __nv_bfloat162* hi = (__nv_bfloat162*)dhi;
    __nv_bfloat162* lo = (__nv_bfloat162*)dlo;
    hi[2 * i + 0] = __nv_bfloat162(h0, h1);
    hi[2 * i + 1] = __nv_bfloat162(h2, h3);
    lo[2 * i + 0] = __nv_bfloat162(l0, l1);
    lo[2 * i + 1] = __nv_bfloat162(l2, l3);
}

__global__ void split_x_kernel(const float* __restrict__ src)  { split_body(src, g_xhi, g_xlo); }
__global__ void split_wq_kernel(const float* __restrict__ src) { split_body(src, g_wq_hi, g_wq_lo); }
__global__ void split_wo_kernel(const float* __restrict__ src) { split_body(src, g_wo_hi, g_wo_lo); }

// ---------------------------------------------------------------------------
// Pipelined WMMA GEMM: C[M,Ncols] = A[M,512](hi+lo) @ W[512,Ncols](hi+lo)
// CTA 128 x (NT*32), 8 warps (4m x 2n), warp 32 x (NT*16), k-chunk 16.
// 3-stage cp.async pipeline (prefetch distance 2), dynamic smem.
// ---------------------------------------------------------------------------
#define ARS 24                        // A smem row stride (halves): 48B rows

template <int NT>                     // n-frags per warp: 4 -> BN=128, 2 -> BN=64
__device__ __forceinline__ void wmma_gemm_body(
    const __nv_bfloat16* Ahi, const __nv_bfloat16* Alo,
    const __nv_bfloat16* Whi, const __nv_bfloat16* Wlo,
    float* C, int Ncols) {
    constexpr int BN  = NT * 32;
    constexpr int BRS = BN + 8;       // B smem row stride (halves), conflict-free
    constexpr int A_STG = 128 * ARS * 2;          // bytes per A stage per array
    constexpr int B_STG = 16 * BRS * 2;           // bytes per B stage per array
    extern __shared__ __align__(16) char dsm[];
    __nv_bfloat16* sAh = (__nv_bfloat16*)(dsm);
    __nv_bfloat16* sAl = (__nv_bfloat16*)(dsm + 3 * A_STG);
    __nv_bfloat16* sBh = (__nv_bfloat16*)(dsm + 6 * A_STG);
    __nv_bfloat16* sBl = (__nv_bfloat16*)(dsm + 6 * A_STG + 3 * B_STG);

    const int tid = threadIdx.x;
    const int w = tid >> 5;
    const int warpm = w & 3, warpn = w >> 2;
    const int row0 = blockIdx.y * 128, col0 = blockIdx.x * BN;

    wmma::fragment<wmma::accumulator, 16, 16, 16, float> acc[2][NT];
#pragma unroll
    for (int mt = 0; mt < 2; mt++)
#pragma unroll
        for (int nt = 0; nt < NT; nt++)
            wmma::fill_fragment(acc[mt][nt], 0.0f);

    // loaders
    const int ar = tid >> 1, aco = (tid & 1) * 8;         // A: 128 rows x 2 chunks
    constexpr int BCH = NT * 4;                           // B 16B-chunks per row
    const bool bact = tid < 16 * BCH;
    const int br = tid / BCH, bco = (tid % BCH) * 8;

    const uint32_t dAh = smem_u32(sAh) + (uint32_t)(ar * ARS + aco) * 2;
    const uint32_t dAl = smem_u32(sAl) + (uint32_t)(ar * ARS + aco) * 2;
    const uint32_t dBh = smem_u32(sBh) + (uint32_t)(br * BRS + bco) * 2;
    const uint32_t dBl = smem_u32(sBl) + (uint32_t)(br * BRS + bco) * 2;

    const __nv_bfloat16* gAh = Ahi + (size_t)(row0 + ar) * 512 + aco;
    const __nv_bfloat16* gAl = Alo + (size_t)(row0 + ar) * 512 + aco;
    const __nv_bfloat16* gBh = Whi + (size_t)br * Ncols + col0 + bco;
    const __nv_bfloat16* gBl = Wlo + (size_t)br * Ncols + col0 + bco;
    const size_t bStep = (size_t)16 * Ncols;

    auto prefetch = [&](int kc) {
        const uint32_t st = (uint32_t)(kc % 3);
        const int k0 = kc * 16;
        CP_ASYNC16(dAh + st * A_STG, gAh + k0);
        CP_ASYNC16(dAl + st * A_STG, gAl + k0);
        if (bact) {
            CP_ASYNC16(dBh + st * B_STG, gBh + (size_t)kc * bStep);
            CP_ASYNC16(dBl + st * B_STG, gBl + (size_t)kc * bStep);
        }
        CP_COMMIT();
    };

    prefetch(0);
    prefetch(1);

    for (int kc = 0; kc < 32; kc++) {
        const int st = kc % 3;
        if (kc < 31) { CP_WAIT1(); } else { CP_WAIT0(); }   // stage kc arrived
        __syncthreads();                 // stage (kc+2)%3 reads retired chip-wide
        if (kc + 2 < 32) prefetch(kc + 2);

        const __nv_bfloat16* aH = sAh + st * (A_STG / 2);
        const __nv_bfloat16* aL = sAl + st * (A_STG / 2);
        const __nv_bfloat16* bH = sBh + st * (B_STG / 2);
        const __nv_bfloat16* bL = sBl + st * (B_STG / 2);

        wmma::fragment<wmma::matrix_a, 16, 16, 16, __nv_bfloat16, wmma::row_major>
            fah[2], fal[2];
#pragma unroll
        for (int mt = 0; mt < 2; mt++) {
            wmma::load_matrix_sync(fah[mt], aH + (warpm * 32 + mt * 16) * ARS, ARS);
            wmma::load_matrix_sync(fal[mt], aL + (warpm * 32 + mt * 16) * ARS, ARS);
        }
#pragma unroll
        for (int nt = 0; nt < NT; nt++) {
            wmma::fragment<wmma::matrix_b, 16, 16, 16, __nv_bfloat16, wmma::row_major>
                fbh, fbl;
            wmma::load_matrix_sync(fbh, bH + warpn * (NT * 16) + nt * 16, BRS);
            wmma::load_matrix_sync(fbl, bL + warpn * (NT * 16) + nt * 16, BRS);
#pragma unroll
            for (int mt = 0; mt < 2; mt++) {
                wmma::mma_sync(acc[mt][nt], fah[mt], fbh, acc[mt][nt]);
                wmma::mma_sync(acc[mt][nt], fah[mt], fbl, acc[mt][nt]);
                wmma::mma_sync(acc[mt][nt], fal[mt], fbh, acc[mt][nt]);
            }
        }
    }

#pragma unroll
    for (int mt = 0; mt < 2; mt++)
#pragma unroll
        for (int nt = 0; nt < NT; nt++)
            wmma::store_matrix_sync(
                &C[(size_t)(row0 + warpm * 32 + mt * 16) * Ncols +
                   col0 + warpn * (NT * 16) + nt * 16],
                acc[mt][nt], Ncols, wmma::mem_row_major);
}

#define QKV_SMEM (6 * (128 * ARS * 2) + 6 * (16 * 136 * 2))   // 62976
#define OUT_SMEM (6 * (128 * ARS * 2) + 6 * (16 * 72 * 2))    // 50688

__global__ __launch_bounds__(256) void qkv_wmma_kernel() {
    wmma_gemm_body<4>(g_xhi, g_xlo, g_wq_hi, g_wq_lo, g_qkv, 3 * DMODEL);
}
__global__ __launch_bounds__(256) void out_wmma_kernel(float* __restrict__ C) {
    wmma_gemm_body<2>(g_ah_hi, g_ah_lo, g_wo_hi, g_wo_lo, C, DMODEL);
}

// Bias add (in place on out): one float4 per thread.
__global__ void bias_add_kernel(float* __restrict__ C, const float* __restrict__ bias) {
    int i = blockIdx.x * blockDim.x + threadIdx.x;     // over N_TOK*DMODEL/4
    int c4 = (i & (DMODEL / 4 - 1)) * 4;
    float4 v = ((float4*)C)[i];
    v.x += bias[c4 + 0]; v.y += bias[c4 + 1];
    v.z += bias[c4 + 2]; v.w += bias[c4 + 3];
    ((float4*)C)[i] = v;
}

// ---------------------------------------------------------------------------
// Attention (proven structure; emits bf16 hi/lo for the out GEMM)
// ---------------------------------------------------------------------------
__global__ void attn_kernel() {
    const float* __restrict__ qkv = g_qkv;
    int r = blockIdx.x;            // 0..63 : (f*32 + h)
    int h = blockIdx.y;            // head
    int f = r >> 5;
    int hp = r & 31;
    int i0 = r * 32;
    int tid = threadIdx.x;
    int ql = tid >> 3;             // query (w coordinate)
    int g  = tid & 7;              // dim group
    int hoff = h * DH;

    __shared__ float Ks[64][33];
    __shared__ float Vs[64][33];

    int iq = i0 + ql;
    int t  = iq + 1;
    const float scale = 0.125f;

    float q[8];
    if (t < N_TOK) {
#pragma unroll
        for (int d = 0; d < 8; d++)
            q[d] = qkv[(size_t)t * 1536 + hoff + g * 8 + d] * scale;
    } else {
#pragma unroll
        for (int d = 0; d < 8; d++) q[d] = 0.f;
    }

    float m, l, acc[8];
    {
        float s = 0.f;
#pragma unroll
        for (int d = 0; d < 8; d++)
            s += q[d] * qkv[512 + hoff + g * 8 + d];
        s += __shfl_xor_sync(0xffffffffu, s, 1);
        s += __shfl_xor_sync(0xffffffffu, s, 2);
        s += __shfl_xor_sync(0xffffffffu, s, 4);
        m = s; l = 1.f;
#pragma unroll
        for (int d = 0; d < 8; d++)
            acc[d] = qkv[1024 + hoff + g * 8 + d];
    }

    for (int df = -2; df <= 2; df++) {
        int nf = f + df;
        if (nf < 0 || nf >= FF) continue;
        for (int dh = -2; dh <= 2; dh++) {
            int nh = hp + dh;
            if (nh < 0 || nh >= HH) continue;
            int j0 = (nf * HH + nh) * WW;

            __syncthreads();
#pragma unroll
            for (int i = 0; i < 2; i++) {
                int id4 = tid + i * 256;
                int c  = id4 >> 4;
                int dv = (id4 & 15) << 2;
                int tok = j0 + 1 + c;
                float4 kk, vv;
                if (tok < N_TOK) {
                    kk = *(const float4*)&qkv[(size_t)tok * 1536 + 512 + hoff + dv];
                    vv = *(const float4*)&qkv[(size_t)tok * 1536 + 1024 + hoff + dv];
                } else {
                    kk = make_float4(0.f, 0.f, 0.f, 0.f);
                    vv = kk;
                }
                Ks[dv + 0][c] = kk.x; Ks[dv + 1][c] = kk.y;
                Ks[dv + 2][c] = kk.z; Ks[dv + 3][c] = kk.w;
                Vs[dv + 0][c] = vv.x; Vs[dv + 1][c] = vv.y;
                Vs[dv + 2][c] = vv.z; Vs[dv + 3][c] = vv.w;
            }
            __syncthreads();

#pragma unroll
            for (int dw = -2; dw <= 2; dw++) {
                int c = ql + dw;
                int j = j0 + c;
                bool valid = ((unsigned)c < 32u) && (j <= iq);
                int cc = min(max(c, 0), 31);
                float s = 0.f;
#pragma unroll
                for (int d = 0; d < 8; d++)
                    s += q[d] * Ks[g * 8 + d][cc];
                s += __shfl_xor_sync(0xffffffffu, s, 1);
                s += __shfl_xor_sync(0xffffffffu, s, 2);
                s += __shfl_xor_sync(0xffffffffu, s, 4);
                if (valid) {
                    float mn = fmaxf(m, s);
                    float corr = __expf(m - mn);
                    float p = __expf(s - mn);
                    l = l * corr + p;
#pragma unroll
                    for (int d = 0; d < 8; d++)
                        acc[d] = acc[d] * corr + p * Vs[g * 8 + d][cc];
                    m = mn;
                }
            }
        }
    }

    if (t < N_TOK) {
        float inv = 1.f / l;
#pragma unroll
        for (int d = 0; d < 8; d++) {
            float v = acc[d] * inv;
            __nv_bfloat16 h16, l16;
            split2(v, h16, l16);
            size_t idx = (size_t)t * DMODEL + hoff + g * 8 + d;
            g_ah_hi[idx] = h16;
            g_ah_lo[idx] = l16;
        }
    }
}

// Output row 0 = V of token 0 (BOS passthrough)
__global__ void bos_kernel() {
    int d = threadIdx.x;           // 512 threads
    float v = g_qkv[1024 + d];
    __nv_bfloat16 h16, l16;
    split2(v, h16, l16);
    g_ah_hi[d] = h16;
    g_ah_lo[d] = l16;
}

// ---------------------------------------------------------------------------
extern "C" void kernel_launch(void* const* d_in, const int* in_sizes, int n_in,
                              void* d_out, int out_size) {
    const float* x     = (const float*)d_in[0];   // [1,2048,512]
    const float* w_qkv = (const float*)d_in[1];   // [512,1536]
    const float* w_out = (const float*)d_in[2];   // [512,512]
    const float* b_out = (const float*)d_in[3];   // [512]
    float* out = (float*)d_out;                   // [1,2048,512]

    cudaFuncSetAttribute(qkv_wmma_kernel,
                         cudaFuncAttributeMaxDynamicSharedMemorySize, QKV_SMEM);
    cudaFuncSetAttribute(out_wmma_kernel,
                         cudaFuncAttributeMaxDynamicSharedMemorySize, OUT_SMEM);

    split_x_kernel<<<N_TOK * DMODEL / 4 / 512, 512>>>(x);
    split_wq_kernel<<<DMODEL * 3 * DMODEL / 4 / 512, 512>>>(w_qkv);
    split_wo_kernel<<<DMODEL * DMODEL / 4 / 512, 512>>>(w_out);

    // QKV GEMM: [2048,512] @ [512,1536], 128x128 tiles -> 192 CTAs
    qkv_wmma_kernel<<<dim3(1536 / 128, N_TOK / 128), 256, QKV_SMEM>>>();

    attn_kernel<<<dim3(64, NH), 256>>>();
    bos_kernel<<<1, 512>>>();

    // Out GEMM: [2048,512] @ [512,512], 128x64 tiles -> 128 CTAs
    out_wmma_kernel<<<dim3(DMODEL / 64, N_TOK / 128), 256, OUT_SMEM>>>(out);
    bias_add_kernel<<<N_TOK * DMODEL / 4 / 512, 512>>>(out, b_out);
}